// round 4
// baseline (speedup 1.0000x reference)
#include <cuda_runtime.h>
#include <cuda_fp16.h>
#include <cstdint>
#include <cstddef>

// ---------------- problem constants ----------------
#define N_HEADS 32
#define D_IN    1408
#define D_HID   256
#define D_OUT   3
#define BATCH   16384

// ---------------- GEMM tiling ----------------
#define M_TILE   128
#define N_TILE   256                 // one full head per CTA
#define K_TILE   64                  // fp16 elems -> 128 B per row
#define K_ITERS  (D_IN / K_TILE)     // 22
#define NSTAGES  4
#define NTHREADS 512                 // 16 warps: 2 (M) x 8 (N), warp tile 64x32

#define A_STAGE_BYTES (M_TILE * K_TILE * 2)       // 16384
#define B_STAGE_BYTES (N_TILE * K_TILE * 2)       // 32768
#define STAGE_BYTES   (A_STAGE_BYTES + B_STAGE_BYTES)  // 49152
#define HDR_BYTES     5664
#define SMEM_SIZE     (6656 + NSTAGES * STAGE_BYTES)   // 203264 <= 227KB

// prepass grid split
#define CONV_BLOCKS  ((BATCH * D_IN) / 4 / 256)              // 22528
#define TRANS_BLOCKS (N_HEADS * (D_IN / 32) * (D_HID / 32))  // 11264

// ---------------- device scratch ----------------
__device__ __half g_Xh[(size_t)BATCH * D_IN];                 // 46.1 MB
__device__ __half g_W1h[(size_t)N_HEADS * D_HID * D_IN];      // 23.1 MB (W1^T, K-major)

// ---------------- helpers ----------------
__device__ __forceinline__ uint32_t smem_u32(const void* p) {
    uint32_t a;
    asm("{ .reg .u64 t; cvta.to.shared.u64 t, %1; cvt.u32.u64 %0, t; }" : "=r"(a) : "l"(p));
    return a;
}

__device__ __forceinline__ void cp_async16(uint32_t saddr, const void* gaddr) {
    asm volatile("cp.async.cg.shared.global [%0], [%1], 16;" :: "r"(saddr), "l"(gaddr));
}

__device__ __forceinline__ void ldmatrix_x4(uint32_t* r, uint32_t addr) {
    asm volatile("ldmatrix.sync.aligned.m8n8.x4.shared.b16 {%0,%1,%2,%3}, [%4];"
                 : "=r"(r[0]), "=r"(r[1]), "=r"(r[2]), "=r"(r[3]) : "r"(addr));
}

__device__ __forceinline__ void mma16816(float* c, const uint32_t* a, uint32_t b0, uint32_t b1) {
    asm volatile(
        "mma.sync.aligned.m16n8k16.row.col.f32.f16.f16.f32 "
        "{%0,%1,%2,%3}, {%4,%5,%6,%7}, {%8,%9}, {%0,%1,%2,%3};"
        : "+f"(c[0]), "+f"(c[1]), "+f"(c[2]), "+f"(c[3])
        : "r"(a[0]), "r"(a[1]), "r"(a[2]), "r"(a[3]), "r"(b0), "r"(b1));
}

// ---------------- merged pre-pass: convert X + transpose W1 ----------------
__global__ void __launch_bounds__(256)
k_prepass(const float* __restrict__ X, const float* __restrict__ W1) {
    const int tid = threadIdx.x;
    if (blockIdx.x < CONV_BLOCKS) {
        const int i = blockIdx.x * 256 + tid;
        const float4 v = reinterpret_cast<const float4*>(X)[i];
        __half2* o2 = reinterpret_cast<__half2*>(g_Xh);
        o2[2 * i + 0] = __floats2half2_rn(v.x, v.y);
        o2[2 * i + 1] = __floats2half2_rn(v.z, v.w);
    } else {
        __shared__ float tile[32][33];
        const int b   = blockIdx.x - CONV_BLOCKS;
        const int h   = b / ((D_IN / 32) * (D_HID / 32));
        const int rem = b % ((D_IN / 32) * (D_HID / 32));
        const int f0  = (rem % (D_IN / 32)) * 32;
        const int o0  = (rem / (D_IN / 32)) * 32;
        const int tx = tid & 31, ty = tid >> 5;     // 32 x 8
        const float* src = W1 + ((size_t)h * D_IN + f0) * D_HID + o0;
        #pragma unroll
        for (int r = 0; r < 32; r += 8)
            tile[ty + r][tx] = src[(size_t)(ty + r) * D_HID + tx];
        __syncthreads();
        __half* dst = g_W1h + ((size_t)h * D_HID + o0) * D_IN + f0;
        #pragma unroll
        for (int r = 0; r < 32; r += 8)
            dst[(size_t)(ty + r) * D_IN + tx] = __float2half_rn(tile[tx][ty + r]);
    }
}

// ---------------- main fused GEMM ----------------
// grid = (BATCH/M_TILE, N_HEADS), 512 threads = 16 warps (2 M x 8 N), warp tile 64x32.
// 4 warps/SMSP for latency hiding. 4-stage cp.async pipeline, single-buffer fragments.
__global__ void __launch_bounds__(NTHREADS, 1)
k_gemm(const float* __restrict__ b1,
       const float* __restrict__ W2,
       const float* __restrict__ b2,
       float* __restrict__ out)
{
    extern __shared__ char smem[];
    float* s_red = (float*)(smem);           // 128*3 floats
    float* s_b1  = (float*)(smem + 1536);    // 256 floats
    float* s_W2  = (float*)(smem + 2560);    // 768 floats
    float* s_b2  = (float*)(smem + 5632);    // 3 floats

    const int tid = threadIdx.x;
    const int w   = tid >> 5;
    const int l   = tid & 31;
    const int mw  = w >> 3;          // 0..1  (M)
    const int nw  = w & 7;           // 0..7  (N)
    const int mtile = blockIdx.x;
    const int head  = blockIdx.y;

    const uint32_t sbase  = smem_u32(smem);
    const uint32_t tiles0 = (sbase + HDR_BYTES + 1023u) & ~1023u;

    // header init
    for (int i = tid; i < M_TILE * 3; i += NTHREADS) s_red[i] = 0.0f;
    for (int i = tid; i < D_HID; i += NTHREADS)      s_b1[i] = b1[head * D_HID + i];
    for (int i = tid; i < D_HID * 3; i += NTHREADS)  s_W2[i] = W2[head * D_HID * 3 + i];
    if (tid < 3)                                     s_b2[tid] = b2[head * 3 + tid];
    __syncthreads();

    const __half* gA = g_Xh  + (size_t)(mtile * M_TILE) * D_IN;
    const __half* gB = g_W1h + (size_t)(head * D_HID) * D_IN;

    // -------- cp.async stage issue (512 thr: 2 A + 4 B chunks of 16B each) --------
    const int r8 = tid >> 3;              // 0..63 (row group)
    const int cc = tid & 7;               // 16B chunk within 128B row
    const uint32_t physc = (uint32_t)(cc ^ (r8 & 7)) * 16;   // XOR swizzle

    auto issue_stage = [&](int slot, int kiter) {
        const uint32_t st = tiles0 + slot * STAGE_BYTES;
        const int k0 = kiter * K_TILE;
        #pragma unroll
        for (int j = 0; j < 2; j++) {                 // A: 128 rows
            const int row = j * 64 + r8;
            cp_async16(st + row * 128 + physc, gA + (size_t)row * D_IN + k0 + cc * 8);
        }
        #pragma unroll
        for (int j = 0; j < 4; j++) {                 // B: 256 rows
            const int row = j * 64 + r8;
            cp_async16(st + A_STAGE_BYTES + row * 128 + physc,
                       gB + (size_t)row * D_IN + k0 + cc * 8);
        }
        asm volatile("cp.async.commit_group;" ::: "memory");
    };

    // -------- accumulators: warp tile 64x32 = 4 m16 x 4 n8 --------
    float acc[4][4][4];
    #pragma unroll
    for (int mi = 0; mi < 4; mi++)
        #pragma unroll
        for (int ni = 0; ni < 4; ni++)
            #pragma unroll
            for (int t = 0; t < 4; t++) acc[mi][ni][t] = 0.0f;

    // ldmatrix lane addressing
    const int a_row_in16 = l & 15;
    const int a_cadd     = l >> 4;
    const int b_row_in16 = ((l >> 4) << 3) + (l & 7);
    const int b_cadd     = (l >> 3) & 1;

    // prologue
    issue_stage(0, 0);
    issue_stage(1, 1);
    issue_stage(2, 2);

    for (int i = 0; i < K_ITERS; i++) {
        asm volatile("cp.async.wait_group 2;" ::: "memory");
        __syncthreads();

        if (i + 3 < K_ITERS) issue_stage((i + 3) & 3, i + 3);
        else                 asm volatile("cp.async.commit_group;" ::: "memory");

        const uint32_t stA = tiles0 + (i & 3) * STAGE_BYTES;
        const uint32_t stB = stA + A_STAGE_BYTES;

        #pragma unroll
        for (int ks = 0; ks < 4; ks++) {             // 4 x k16
            const int c0 = ks * 2;
            uint32_t af[4][4];
            #pragma unroll
            for (int mi = 0; mi < 4; mi++) {
                const int row = mw * 64 + mi * 16 + a_row_in16;
                const int ch  = c0 + a_cadd;
                ldmatrix_x4(af[mi], stA + row * 128 + ((uint32_t)(ch ^ (row & 7)) * 16));
            }
            uint32_t bf[2][4];
            #pragma unroll
            for (int nj = 0; nj < 2; nj++) {         // 2 x n16
                const int row = nw * 32 + nj * 16 + b_row_in16;
                const int ch  = c0 + b_cadd;
                ldmatrix_x4(bf[nj], stB + row * 128 + ((uint32_t)(ch ^ (row & 7)) * 16));
            }
            #pragma unroll
            for (int mi = 0; mi < 4; mi++)
                #pragma unroll
                for (int nj = 0; nj < 2; nj++) {
                    mma16816(acc[mi][2 * nj],     af[mi], bf[nj][0], bf[nj][1]);
                    mma16816(acc[mi][2 * nj + 1], af[mi], bf[nj][2], bf[nj][3]);
                }
        }
    }

    // -------- epilogue: h = relu(acc + b1), partial out = h @ W2 --------
    float part[8][3];
    #pragma unroll
    for (int r = 0; r < 8; r++) { part[r][0] = part[r][1] = part[r][2] = 0.0f; }

    #pragma unroll
    for (int mi = 0; mi < 4; mi++)
        #pragma unroll
        for (int ni = 0; ni < 4; ni++)
            #pragma unroll
            for (int t2 = 0; t2 < 4; t2++) {
                const int q = t2 >> 1, t = t2 & 1;
                const int n = nw * 32 + ni * 8 + (l & 3) * 2 + t;
                float h = acc[mi][ni][t2] + s_b1[n];
                h = fmaxf(h, 0.0f);
                part[mi * 2 + q][0] = fmaf(h, s_W2[n * 3 + 0], part[mi * 2 + q][0]);
                part[mi * 2 + q][1] = fmaf(h, s_W2[n * 3 + 1], part[mi * 2 + q][1]);
                part[mi * 2 + q][2] = fmaf(h, s_W2[n * 3 + 2], part[mi * 2 + q][2]);
            }

    // reduce over the 4 lanes sharing each row (l&3 varies)
    #pragma unroll
    for (int r = 0; r < 8; r++)
        #pragma unroll
        for (int p = 0; p < 3; p++) {
            part[r][p] += __shfl_xor_sync(0xffffffffu, part[r][p], 1);
            part[r][p] += __shfl_xor_sync(0xffffffffu, part[r][p], 2);
        }

    if ((l & 3) == 0) {
        #pragma unroll
        for (int mi = 0; mi < 4; mi++)
            #pragma unroll
            for (int q = 0; q < 2; q++) {
                const int row = mw * 64 + mi * 16 + (l >> 2) + q * 8;
                atomicAdd(&s_red[row * 3 + 0], part[mi * 2 + q][0]);
                atomicAdd(&s_red[row * 3 + 1], part[mi * 2 + q][1]);
                atomicAdd(&s_red[row * 3 + 2], part[mi * 2 + q][2]);
            }
    }
    __syncthreads();

    if (tid < M_TILE) {
        float* po = out + (size_t)(mtile * M_TILE + tid) * (N_HEADS * D_OUT) + head * 3;
        po[0] = s_red[tid * 3 + 0] + s_b2[0];
        po[1] = s_red[tid * 3 + 1] + s_b2[1];
        po[2] = s_red[tid * 3 + 2] + s_b2[2];
    }
}

// ---------------- host launch ----------------
extern "C" void kernel_launch(void* const* d_in, const int* in_sizes, int n_in,
                              void* d_out, int out_size) {
    const float* X  = (const float*)d_in[0];
    const float* W1 = (const float*)d_in[1];
    const float* b1 = (const float*)d_in[2];
    const float* W2 = (const float*)d_in[3];
    const float* b2 = (const float*)d_in[4];
    float* out = (float*)d_out;
    (void)in_sizes; (void)n_in; (void)out_size;

    k_prepass<<<CONV_BLOCKS + TRANS_BLOCKS, 256>>>(X, W1);

    static bool attr_set = false;
    if (!attr_set) {
        cudaFuncSetAttribute(k_gemm, cudaFuncAttributeMaxDynamicSharedMemorySize, SMEM_SIZE);
        attr_set = true;
    }
    dim3 grid(BATCH / M_TILE, N_HEADS);
    k_gemm<<<grid, NTHREADS, SMEM_SIZE>>>(b1, W2, b2, out);
}

// round 5
// speedup vs baseline: 1.1394x; 1.1394x over previous
#include <cuda_runtime.h>
#include <cuda_fp16.h>
#include <cstdint>
#include <cstddef>

// ---------------- problem constants ----------------
#define N_HEADS 32
#define D_IN    1408
#define D_HID   256
#define D_OUT   3
#define BATCH   16384

// ---------------- GEMM tiling ----------------
#define M_TILE   128
#define N_TILE   256                 // one full head per CTA
#define K_TILE   128                 // fp16 elems -> 256 B per row
#define K_ITERS  (D_IN / K_TILE)     // 11
#define NSTAGES  2
#define NTHREADS 256                 // 8 warps: 2 (M) x 4 (N), warp tile 64x64

#define ROW_BYTES     256
#define A_STAGE_BYTES (M_TILE * ROW_BYTES)        // 32768
#define B_STAGE_BYTES (N_TILE * ROW_BYTES)        // 65536
#define STAGE_BYTES   (A_STAGE_BYTES + B_STAGE_BYTES)   // 98304
#define HDR_BYTES     5664
#define SMEM_SIZE     (6656 + NSTAGES * STAGE_BYTES)    // 203264 <= 227KB

// prepass grid split
#define CONV_BLOCKS  ((BATCH * D_IN) / 4 / 256)              // 22528
#define TRANS_BLOCKS (N_HEADS * (D_IN / 32) * (D_HID / 32))  // 11264

// ---------------- device scratch ----------------
__device__ __half g_Xh[(size_t)BATCH * D_IN];                 // 46.1 MB
__device__ __half g_W1h[(size_t)N_HEADS * D_HID * D_IN];      // 23.1 MB (W1^T, K-major)

// ---------------- helpers ----------------
__device__ __forceinline__ uint32_t smem_u32(const void* p) {
    uint32_t a;
    asm("{ .reg .u64 t; cvta.to.shared.u64 t, %1; cvt.u32.u64 %0, t; }" : "=r"(a) : "l"(p));
    return a;
}

__device__ __forceinline__ void cp_async16(uint32_t saddr, const void* gaddr) {
    asm volatile("cp.async.cg.shared.global [%0], [%1], 16;" :: "r"(saddr), "l"(gaddr));
}

__device__ __forceinline__ void ldmatrix_x4(uint32_t* r, uint32_t addr) {
    asm volatile("ldmatrix.sync.aligned.m8n8.x4.shared.b16 {%0,%1,%2,%3}, [%4];"
                 : "=r"(r[0]), "=r"(r[1]), "=r"(r[2]), "=r"(r[3]) : "r"(addr));
}

__device__ __forceinline__ void mma16816(float* c, const uint32_t* a, uint32_t b0, uint32_t b1) {
    asm volatile(
        "mma.sync.aligned.m16n8k16.row.col.f32.f16.f16.f32 "
        "{%0,%1,%2,%3}, {%4,%5,%6,%7}, {%8,%9}, {%0,%1,%2,%3};"
        : "+f"(c[0]), "+f"(c[1]), "+f"(c[2]), "+f"(c[3])
        : "r"(a[0]), "r"(a[1]), "r"(a[2]), "r"(a[3]), "r"(b0), "r"(b1));
}

// ---------------- merged pre-pass: convert X + transpose W1 ----------------
__global__ void __launch_bounds__(256)
k_prepass(const float* __restrict__ X, const float* __restrict__ W1) {
    const int tid = threadIdx.x;
    if (blockIdx.x < CONV_BLOCKS) {
        const int i = blockIdx.x * 256 + tid;
        const float4 v = reinterpret_cast<const float4*>(X)[i];
        __half2* o2 = reinterpret_cast<__half2*>(g_Xh);
        o2[2 * i + 0] = __floats2half2_rn(v.x, v.y);
        o2[2 * i + 1] = __floats2half2_rn(v.z, v.w);
    } else {
        __shared__ float tile[32][33];
        const int b   = blockIdx.x - CONV_BLOCKS;
        const int h   = b / ((D_IN / 32) * (D_HID / 32));
        const int rem = b % ((D_IN / 32) * (D_HID / 32));
        const int f0  = (rem % (D_IN / 32)) * 32;
        const int o0  = (rem / (D_IN / 32)) * 32;
        const int tx = tid & 31, ty = tid >> 5;     // 32 x 8
        const float* src = W1 + ((size_t)h * D_IN + f0) * D_HID + o0;
        #pragma unroll
        for (int r = 0; r < 32; r += 8)
            tile[ty + r][tx] = src[(size_t)(ty + r) * D_HID + tx];
        __syncthreads();
        __half* dst = g_W1h + ((size_t)h * D_HID + o0) * D_IN + f0;
        #pragma unroll
        for (int r = 0; r < 32; r += 8)
            dst[(size_t)(ty + r) * D_IN + tx] = __float2half_rn(tile[tx][ty + r]);
    }
}

// ---------------- main fused GEMM ----------------
// grid = (BATCH/M_TILE, N_HEADS), 256 threads (8 warps: 2 M x 4 N), warp tile 64x64.
// K_TILE=128, 2-stage pipeline: ONE barrier per 8 k16-steps; cp.async spread in
// 6 slices across the k-steps; register double-buffered ldmatrix fragments.
__global__ void __launch_bounds__(NTHREADS, 1)
k_gemm(const float* __restrict__ b1,
       const float* __restrict__ W2,
       const float* __restrict__ b2,
       float* __restrict__ out)
{
    extern __shared__ char smem[];
    float* s_red = (float*)(smem);           // 128*3 floats
    float* s_b1  = (float*)(smem + 1536);    // 256 floats
    float* s_W2  = (float*)(smem + 2560);    // 768 floats
    float* s_b2  = (float*)(smem + 5632);    // 3 floats

    const int tid = threadIdx.x;
    const int w   = tid >> 5;
    const int l   = tid & 31;
    const int mw  = w >> 2;          // 0..1  (M)
    const int nw  = w & 3;           // 0..3  (N)
    const int mtile = blockIdx.x;
    const int head  = blockIdx.y;

    const uint32_t sbase  = smem_u32(smem);
    const uint32_t tiles0 = (sbase + HDR_BYTES + 1023u) & ~1023u;

    // header init
    for (int i = tid; i < M_TILE * 3; i += NTHREADS) s_red[i] = 0.0f;
    for (int i = tid; i < D_HID; i += NTHREADS)      s_b1[i] = b1[head * D_HID + i];
    for (int i = tid; i < D_HID * 3; i += NTHREADS)  s_W2[i] = W2[head * D_HID * 3 + i];
    if (tid < 3)                                     s_b2[tid] = b2[head * 3 + tid];
    __syncthreads();

    const __half* gA = g_Xh  + (size_t)(mtile * M_TILE) * D_IN;
    const __half* gB = g_W1h + (size_t)(head * D_HID) * D_IN;

    // -------- cp.async: 24 chunks of 16B per thread per stage, in 6 slices of 4 --------
    // rows are 256B: 16 chunks; swizzle XORs low-3 chunk bits with row&7, half-select bit -> +128B
    const int r16 = tid >> 4;             // 0..15 (row group; row&7 == r16&7)
    const int cc  = tid & 15;             // 16B chunk within 256B row
    const uint32_t physoff = (uint32_t)((cc & 7) ^ (r16 & 7)) * 16 + (uint32_t)(cc >> 3) * 128;

    auto issue_slice = [&](int slot, int kiter, int slice) {
        const uint32_t st = tiles0 + slot * STAGE_BYTES;
        const int k0 = kiter * K_TILE;
        if (slice < 2) {                               // A: 128 rows in 2 slices
            #pragma unroll
            for (int j = 0; j < 4; j++) {
                const int row = (slice * 4 + j) * 16 + r16;
                cp_async16(st + row * ROW_BYTES + physoff,
                           gA + (size_t)row * D_IN + k0 + cc * 8);
            }
        } else {                                       // B: 256 rows in 4 slices
            #pragma unroll
            for (int j = 0; j < 4; j++) {
                const int row = ((slice - 2) * 4 + j) * 16 + r16;
                cp_async16(st + A_STAGE_BYTES + row * ROW_BYTES + physoff,
                           gB + (size_t)row * D_IN + k0 + cc * 8);
            }
        }
    };

    // -------- accumulators: warp tile 64x64 = 4 m16 x 8 n8 --------
    float acc[4][8][4];
    #pragma unroll
    for (int mi = 0; mi < 4; mi++)
        #pragma unroll
        for (int ni = 0; ni < 8; ni++)
            #pragma unroll
            for (int t = 0; t < 4; t++) acc[mi][ni][t] = 0.0f;

    // ldmatrix lane addressing
    const int a_row_in16 = l & 15;
    const int a_cadd     = l >> 4;
    const int b_row_in16 = ((l >> 4) << 3) + (l & 7);
    const int b_cadd     = (l >> 3) & 1;

    uint32_t af[2][4][4];
    uint32_t bf[2][4][4];

    auto load_frags = [&](int buf, uint32_t stA, uint32_t stB, int ks) {
        // k16 step ks (0..7): chunk index ch in [0,16); half = ch>>3, within-half c = ch&7
        #pragma unroll
        for (int mi = 0; mi < 4; mi++) {
            const int row = mw * 64 + mi * 16 + a_row_in16;
            const int ch  = ks * 2 + a_cadd;
            ldmatrix_x4(af[buf][mi],
                stA + row * ROW_BYTES + ((uint32_t)(ch >> 3) << 7)
                    + ((uint32_t)((ch & 7) ^ (row & 7)) << 4));
        }
        #pragma unroll
        for (int nj = 0; nj < 4; nj++) {
            const int row = nw * 64 + nj * 16 + b_row_in16;
            const int ch  = ks * 2 + b_cadd;
            ldmatrix_x4(bf[buf][nj],
                stB + row * ROW_BYTES + ((uint32_t)(ch >> 3) << 7)
                    + ((uint32_t)((ch & 7) ^ (row & 7)) << 4));
        }
    };

    auto do_mmas = [&](int buf) {
        #pragma unroll
        for (int mi = 0; mi < 4; mi++)
            #pragma unroll
            for (int nj = 0; nj < 4; nj++) {
                mma16816(acc[mi][2 * nj],     af[buf][mi], bf[buf][nj][0], bf[buf][nj][1]);
                mma16816(acc[mi][2 * nj + 1], af[buf][mi], bf[buf][nj][2], bf[buf][nj][3]);
            }
    };

    // prologue: fill stage 0
    #pragma unroll
    for (int s = 0; s < 6; s++) issue_slice(0, 0, s);
    asm volatile("cp.async.commit_group;" ::: "memory");

    for (int i = 0; i < K_ITERS; i++) {
        asm volatile("cp.async.wait_group 0;" ::: "memory");
        __syncthreads();

        const uint32_t stA = tiles0 + (i & 1) * STAGE_BYTES;
        const uint32_t stB = stA + A_STAGE_BYTES;
        const bool pre  = (i + 1 < K_ITERS);
        const int nslot = (i + 1) & 1;

        load_frags(0, stA, stB, 0);

        #pragma unroll
        for (int ks = 0; ks < 8; ks++) {
            if (ks < 6 && pre) {
                issue_slice(nslot, i + 1, ks);
                if (ks == 5) asm volatile("cp.async.commit_group;" ::: "memory");
            }
            if (ks < 7) load_frags((ks + 1) & 1, stA, stB, ks + 1);
            do_mmas(ks & 1);
        }
    }

    // -------- epilogue: h = relu(acc + b1), partial out = h @ W2 --------
    float part[8][3];
    #pragma unroll
    for (int r = 0; r < 8; r++) { part[r][0] = part[r][1] = part[r][2] = 0.0f; }

    #pragma unroll
    for (int mi = 0; mi < 4; mi++)
        #pragma unroll
        for (int ni = 0; ni < 8; ni++)
            #pragma unroll
            for (int t2 = 0; t2 < 4; t2++) {
                const int q = t2 >> 1, t = t2 & 1;
                const int n = nw * 64 + ni * 8 + (l & 3) * 2 + t;
                float h = acc[mi][ni][t2] + s_b1[n];
                h = fmaxf(h, 0.0f);
                part[mi * 2 + q][0] = fmaf(h, s_W2[n * 3 + 0], part[mi * 2 + q][0]);
                part[mi * 2 + q][1] = fmaf(h, s_W2[n * 3 + 1], part[mi * 2 + q][1]);
                part[mi * 2 + q][2] = fmaf(h, s_W2[n * 3 + 2], part[mi * 2 + q][2]);
            }

    #pragma unroll
    for (int r = 0; r < 8; r++)
        #pragma unroll
        for (int p = 0; p < 3; p++) {
            part[r][p] += __shfl_xor_sync(0xffffffffu, part[r][p], 1);
            part[r][p] += __shfl_xor_sync(0xffffffffu, part[r][p], 2);
        }

    if ((l & 3) == 0) {
        #pragma unroll
        for (int mi = 0; mi < 4; mi++)
            #pragma unroll
            for (int q = 0; q < 2; q++) {
                const int row = mw * 64 + mi * 16 + (l >> 2) + q * 8;
                atomicAdd(&s_red[row * 3 + 0], part[mi * 2 + q][0]);
                atomicAdd(&s_red[row * 3 + 1], part[mi * 2 + q][1]);
                atomicAdd(&s_red[row * 3 + 2], part[mi * 2 + q][2]);
            }
    }
    __syncthreads();

    if (tid < M_TILE) {
        float* po = out + (size_t)(mtile * M_TILE + tid) * (N_HEADS * D_OUT) + head * 3;
        po[0] = s_red[tid * 3 + 0] + s_b2[0];
        po[1] = s_red[tid * 3 + 1] + s_b2[1];
        po[2] = s_red[tid * 3 + 2] + s_b2[2];
    }
}

// ---------------- host launch ----------------
extern "C" void kernel_launch(void* const* d_in, const int* in_sizes, int n_in,
                              void* d_out, int out_size) {
    const float* X  = (const float*)d_in[0];
    const float* W1 = (const float*)d_in[1];
    const float* b1 = (const float*)d_in[2];
    const float* W2 = (const float*)d_in[3];
    const float* b2 = (const float*)d_in[4];
    float* out = (float*)d_out;
    (void)in_sizes; (void)n_in; (void)out_size;

    k_prepass<<<CONV_BLOCKS + TRANS_BLOCKS, 256>>>(X, W1);

    static bool attr_set = false;
    if (!attr_set) {
        cudaFuncSetAttribute(k_gemm, cudaFuncAttributeMaxDynamicSharedMemorySize, SMEM_SIZE);
        attr_set = true;
    }
    dim3 grid(BATCH / M_TILE, N_HEADS);
    k_gemm<<<grid, NTHREADS, SMEM_SIZE>>>(b1, W2, b2, out);
}

// round 6
// speedup vs baseline: 1.1478x; 1.0074x over previous
#include <cuda_runtime.h>
#include <cuda_fp16.h>
#include <cstdint>
#include <cstddef>

// ---------------- problem constants ----------------
#define N_HEADS 32
#define D_IN    1408
#define D_HID   256
#define D_OUT   3
#define BATCH   16384

// ---------------- GEMM tiling ----------------
#define M_TILE   128
#define N_TILE   128                 // HALF a head per CTA (nhalf splits D_HID)
#define K_TILE   64                  // fp16 elems -> 128 B per row
#define K_ITERS  (D_IN / K_TILE)     // 22
#define NSTAGES  3
#define NTHREADS 256                 // 8 warps: 2 (M) x 4 (N), warp tile 64x32

#define ROW_BYTES     128
#define A_STAGE_BYTES (M_TILE * ROW_BYTES)        // 16384
#define B_STAGE_BYTES (N_TILE * ROW_BYTES)        // 16384
#define STAGE_BYTES   (A_STAGE_BYTES + B_STAGE_BYTES)   // 32768
#define HDR_BYTES     3584
#define SMEM_SIZE     (4096 + NSTAGES * STAGE_BYTES)    // 102400; x2 CTAs = 200KB <= 227KB

// prepass grid split
#define CONV_BLOCKS  ((BATCH * D_IN) / 4 / 256)              // 22528
#define TRANS_BLOCKS (N_HEADS * (D_IN / 32) * (D_HID / 32))  // 11264

// ---------------- device scratch ----------------
__device__ __half g_Xh[(size_t)BATCH * D_IN];                 // 46.1 MB
__device__ __half g_W1h[(size_t)N_HEADS * D_HID * D_IN];      // 23.1 MB (W1^T, K-major)
__device__ float  g_part[2ULL * BATCH * (N_HEADS * D_OUT)];   // 12.6 MB partial sums

// ---------------- helpers ----------------
__device__ __forceinline__ uint32_t smem_u32(const void* p) {
    uint32_t a;
    asm("{ .reg .u64 t; cvta.to.shared.u64 t, %1; cvt.u32.u64 %0, t; }" : "=r"(a) : "l"(p));
    return a;
}

__device__ __forceinline__ void cp_async16(uint32_t saddr, const void* gaddr) {
    asm volatile("cp.async.cg.shared.global [%0], [%1], 16;" :: "r"(saddr), "l"(gaddr));
}

__device__ __forceinline__ void ldmatrix_x4(uint32_t* r, uint32_t addr) {
    asm volatile("ldmatrix.sync.aligned.m8n8.x4.shared.b16 {%0,%1,%2,%3}, [%4];"
                 : "=r"(r[0]), "=r"(r[1]), "=r"(r[2]), "=r"(r[3]) : "r"(addr));
}

__device__ __forceinline__ void mma16816(float* c, const uint32_t* a, uint32_t b0, uint32_t b1) {
    asm volatile(
        "mma.sync.aligned.m16n8k16.row.col.f32.f16.f16.f32 "
        "{%0,%1,%2,%3}, {%4,%5,%6,%7}, {%8,%9}, {%0,%1,%2,%3};"
        : "+f"(c[0]), "+f"(c[1]), "+f"(c[2]), "+f"(c[3])
        : "r"(a[0]), "r"(a[1]), "r"(a[2]), "r"(a[3]), "r"(b0), "r"(b1));
}

// ---------------- merged pre-pass: convert X + transpose W1 ----------------
__global__ void __launch_bounds__(256)
k_prepass(const float* __restrict__ X, const float* __restrict__ W1) {
    const int tid = threadIdx.x;
    if (blockIdx.x < CONV_BLOCKS) {
        const int i = blockIdx.x * 256 + tid;
        const float4 v = reinterpret_cast<const float4*>(X)[i];
        __half2* o2 = reinterpret_cast<__half2*>(g_Xh);
        o2[2 * i + 0] = __floats2half2_rn(v.x, v.y);
        o2[2 * i + 1] = __floats2half2_rn(v.z, v.w);
    } else {
        __shared__ float tile[32][33];
        const int b   = blockIdx.x - CONV_BLOCKS;
        const int h   = b / ((D_IN / 32) * (D_HID / 32));
        const int rem = b % ((D_IN / 32) * (D_HID / 32));
        const int f0  = (rem % (D_IN / 32)) * 32;
        const int o0  = (rem / (D_IN / 32)) * 32;
        const int tx = tid & 31, ty = tid >> 5;     // 32 x 8
        const float* src = W1 + ((size_t)h * D_IN + f0) * D_HID + o0;
        #pragma unroll
        for (int r = 0; r < 32; r += 8)
            tile[ty + r][tx] = src[(size_t)(ty + r) * D_HID + tx];
        __syncthreads();
        __half* dst = g_W1h + ((size_t)h * D_HID + o0) * D_IN + f0;
        #pragma unroll
        for (int r = 0; r < 32; r += 8)
            dst[(size_t)(ty + r) * D_IN + tx] = __float2half_rn(tile[tx][ty + r]);
    }
}

// ---------------- main fused GEMM (partial heads) ----------------
// grid = (BATCH/128, N_HEADS*2). CTA tile 128x128 (half head). 2 CTAs/SM:
// one CTA's HMMAs cover the other's barrier/prologue/epilogue bubbles.
__global__ void __launch_bounds__(NTHREADS, 2)
k_gemm(const float* __restrict__ b1,
       const float* __restrict__ W2,
       float* __restrict__ outp_unused)
{
    extern __shared__ char smem[];
    float* s_red = (float*)(smem);           // 128*3 floats  [0,1536)
    float* s_b1  = (float*)(smem + 1536);    // 128 floats    [1536,2048)
    float* s_W2  = (float*)(smem + 2048);    // 384 floats    [2048,3584)

    const int tid = threadIdx.x;
    const int w   = tid >> 5;
    const int l   = tid & 31;
    const int mw  = w >> 2;          // 0..1  (M)
    const int nw  = w & 3;           // 0..3  (N, 32 cols each)
    const int mtile = blockIdx.x;
    const int head  = blockIdx.y >> 1;
    const int nhalf = blockIdx.y & 1;

    const uint32_t sbase  = smem_u32(smem);
    const uint32_t tiles0 = (sbase + HDR_BYTES + 1023u) & ~1023u;

    // header init
    for (int i = tid; i < M_TILE * 3; i += NTHREADS) s_red[i] = 0.0f;
    if (tid < N_TILE)                       s_b1[tid] = b1[head * D_HID + nhalf * N_TILE + tid];
    for (int i = tid; i < N_TILE * 3; i += NTHREADS)
        s_W2[i] = W2[head * D_HID * 3 + nhalf * N_TILE * 3 + i];
    __syncthreads();

    const __half* gA = g_Xh  + (size_t)(mtile * M_TILE) * D_IN;
    const __half* gB = g_W1h + ((size_t)head * D_HID + nhalf * N_TILE) * D_IN;

    // -------- cp.async: 8 chunks of 16B per thread per stage (A 4 + B 4) --------
    const int r8 = tid >> 3;              // 0..31 (row group)
    const int cc = tid & 7;               // 16B chunk within 128B row
    const uint32_t physc = (uint32_t)(cc ^ (r8 & 7)) * 16;   // XOR swizzle

    auto issue_A = [&](int slot, int kiter) {
        const uint32_t st = tiles0 + slot * STAGE_BYTES;
        const int k0 = kiter * K_TILE;
        #pragma unroll
        for (int j = 0; j < 4; j++) {
            const int row = j * 32 + r8;
            cp_async16(st + row * ROW_BYTES + physc, gA + (size_t)row * D_IN + k0 + cc * 8);
        }
    };
    auto issue_B = [&](int slot, int kiter) {
        const uint32_t st = tiles0 + slot * STAGE_BYTES + A_STAGE_BYTES;
        const int k0 = kiter * K_TILE;
        #pragma unroll
        for (int j = 0; j < 4; j++) {
            const int row = j * 32 + r8;
            cp_async16(st + row * ROW_BYTES + physc, gB + (size_t)row * D_IN + k0 + cc * 8);
        }
    };

    // -------- accumulators: warp tile 64x32 = 4 m16 x 4 n8 --------
    float acc[4][4][4];
    #pragma unroll
    for (int mi = 0; mi < 4; mi++)
        #pragma unroll
        for (int ni = 0; ni < 4; ni++)
            #pragma unroll
            for (int t = 0; t < 4; t++) acc[mi][ni][t] = 0.0f;

    // ldmatrix lane addressing
    const int a_row_in16 = l & 15;
    const int a_cadd     = l >> 4;
    const int b_row_in16 = ((l >> 4) << 3) + (l & 7);
    const int b_cadd     = (l >> 3) & 1;

    // prologue: stages 0 and 1
    issue_A(0, 0); issue_B(0, 0);
    asm volatile("cp.async.commit_group;" ::: "memory");
    issue_A(1, 1); issue_B(1, 1);
    asm volatile("cp.async.commit_group;" ::: "memory");

    int slot = 0;
    for (int i = 0; i < K_ITERS; i++) {
        asm volatile("cp.async.wait_group 1;" ::: "memory");
        __syncthreads();

        const uint32_t stA = tiles0 + slot * STAGE_BYTES;
        const uint32_t stB = stA + A_STAGE_BYTES;
        const bool pre   = (i + 2 < K_ITERS);
        const int  nslot = (slot + 2 >= NSTAGES) ? slot + 2 - NSTAGES : slot + 2;

        #pragma unroll
        for (int ks = 0; ks < 4; ks++) {             // 4 x k16
            if (ks == 0 && pre) issue_A(nslot, i + 2);
            if (ks == 1) {
                if (pre) issue_B(nslot, i + 2);
                asm volatile("cp.async.commit_group;" ::: "memory");   // one group per iter
            }
            const int c0 = ks * 2;
            uint32_t af[4][4];
            #pragma unroll
            for (int mi = 0; mi < 4; mi++) {
                const int row = mw * 64 + mi * 16 + a_row_in16;
                const int ch  = c0 + a_cadd;
                ldmatrix_x4(af[mi], stA + row * ROW_BYTES + ((uint32_t)(ch ^ (row & 7)) << 4));
            }
            uint32_t bf[2][4];
            #pragma unroll
            for (int nj = 0; nj < 2; nj++) {
                const int row = nw * 32 + nj * 16 + b_row_in16;
                const int ch  = c0 + b_cadd;
                ldmatrix_x4(bf[nj], stB + row * ROW_BYTES + ((uint32_t)(ch ^ (row & 7)) << 4));
            }
            #pragma unroll
            for (int mi = 0; mi < 4; mi++)
                #pragma unroll
                for (int nj = 0; nj < 2; nj++) {
                    mma16816(acc[mi][2 * nj],     af[mi], bf[nj][0], bf[nj][1]);
                    mma16816(acc[mi][2 * nj + 1], af[mi], bf[nj][2], bf[nj][3]);
                }
        }
        slot = (slot + 1 >= NSTAGES) ? 0 : slot + 1;
    }

    // -------- epilogue: h = relu(acc + b1), partial out = h @ W2 (local n range) --------
    float part[8][3];
    #pragma unroll
    for (int r = 0; r < 8; r++) { part[r][0] = part[r][1] = part[r][2] = 0.0f; }

    #pragma unroll
    for (int mi = 0; mi < 4; mi++)
        #pragma unroll
        for (int ni = 0; ni < 4; ni++)
            #pragma unroll
            for (int t2 = 0; t2 < 4; t2++) {
                const int q = t2 >> 1, t = t2 & 1;
                const int n = nw * 32 + ni * 8 + (l & 3) * 2 + t;   // local 0..127
                float h = acc[mi][ni][t2] + s_b1[n];
                h = fmaxf(h, 0.0f);
                part[mi * 2 + q][0] = fmaf(h, s_W2[n * 3 + 0], part[mi * 2 + q][0]);
                part[mi * 2 + q][1] = fmaf(h, s_W2[n * 3 + 1], part[mi * 2 + q][1]);
                part[mi * 2 + q][2] = fmaf(h, s_W2[n * 3 + 2], part[mi * 2 + q][2]);
            }

    #pragma unroll
    for (int r = 0; r < 8; r++)
        #pragma unroll
        for (int p = 0; p < 3; p++) {
            part[r][p] += __shfl_xor_sync(0xffffffffu, part[r][p], 1);
            part[r][p] += __shfl_xor_sync(0xffffffffu, part[r][p], 2);
        }

    if ((l & 3) == 0) {
        #pragma unroll
        for (int mi = 0; mi < 4; mi++)
            #pragma unroll
            for (int q = 0; q < 2; q++) {
                const int row = mw * 64 + mi * 16 + (l >> 2) + q * 8;
                atomicAdd(&s_red[row * 3 + 0], part[mi * 2 + q][0]);
                atomicAdd(&s_red[row * 3 + 1], part[mi * 2 + q][1]);
                atomicAdd(&s_red[row * 3 + 2], part[mi * 2 + q][2]);
            }
    }
    __syncthreads();

    if (tid < M_TILE) {
        float* pp = g_part + (size_t)nhalf * BATCH * (N_HEADS * D_OUT)
                  + (size_t)(mtile * M_TILE + tid) * (N_HEADS * D_OUT) + head * 3;
        pp[0] = s_red[tid * 3 + 0];
        pp[1] = s_red[tid * 3 + 1];
        pp[2] = s_red[tid * 3 + 2];
    }
    (void)outp_unused;
}

// ---------------- reduce: out = part0 + part1 + b2 (deterministic) ----------------
__global__ void __launch_bounds__(256)
k_reduce(const float* __restrict__ b2, float* __restrict__ out) {
    const int i = blockIdx.x * 256 + threadIdx.x;      // float4 index
    const int ntot4 = BATCH * (N_HEADS * D_OUT) / 4;   // 393216
    if (i >= ntot4) return;
    const float4 p0 = reinterpret_cast<const float4*>(g_part)[i];
    const float4 p1 = reinterpret_cast<const float4*>(g_part + (size_t)BATCH * 96)[i];
    const int c = (i * 4) % 96;                         // 96 % 4 == 0 -> aligned in-row
    float4 o;
    o.x = p0.x + p1.x + __ldg(&b2[c + 0]);
    o.y = p0.y + p1.y + __ldg(&b2[c + 1]);
    o.z = p0.z + p1.z + __ldg(&b2[c + 2]);
    o.w = p0.w + p1.w + __ldg(&b2[c + 3]);
    reinterpret_cast<float4*>(out)[i] = o;
}

// ---------------- host launch ----------------
extern "C" void kernel_launch(void* const* d_in, const int* in_sizes, int n_in,
                              void* d_out, int out_size) {
    const float* X  = (const float*)d_in[0];
    const float* W1 = (const float*)d_in[1];
    const float* b1 = (const float*)d_in[2];
    const float* W2 = (const float*)d_in[3];
    const float* b2 = (const float*)d_in[4];
    float* out = (float*)d_out;
    (void)in_sizes; (void)n_in; (void)out_size;

    k_prepass<<<CONV_BLOCKS + TRANS_BLOCKS, 256>>>(X, W1);

    static bool attr_set = false;
    if (!attr_set) {
        cudaFuncSetAttribute(k_gemm, cudaFuncAttributeMaxDynamicSharedMemorySize, SMEM_SIZE);
        attr_set = true;
    }
    dim3 grid(BATCH / M_TILE, N_HEADS * 2);   // (128, 64)
    k_gemm<<<grid, NTHREADS, SMEM_SIZE>>>(b1, W2, out);

    const int ntot4 = BATCH * (N_HEADS * D_OUT) / 4;
    k_reduce<<<(ntot4 + 255) / 256, 256>>>(b2, out);
}